// round 15
// baseline (speedup 1.0000x reference)
#include <cuda_runtime.h>
#include <cuda_fp16.h>
#include <cstdint>

// Problem constants
#define N_FEAT  65536
#define N_PROTO 512
#define DIMK    256

#define BLK_M   128                 // feature rows per CTA (8 warps x 16 rows)
#define BLK_N   64                  // protos per chunk
#define N_CHUNKS 8

// SMEM layout (bytes): NO A tile, NO fsq — A lives in registers.
#define SM_PSQ   0                          // 512 floats = 2048 B
#define SM_B0    4096                       // 4 pair-slabs * 16 s * 512 B = 32768
#define SM_B1    (SM_B0 + 32768)
#define SMEM_TOTAL (SM_B1 + 32768)          // 69632 B

// pack float2 -> fp16x2 (x -> low half)
__device__ __forceinline__ uint32_t pk(float2 f) {
    __half2 h = __floats2half2_rn(f.x, f.y);
    return *(uint32_t*)&h;
}

// m16n8k16 fp16 MMA, fp32 accumulate
__device__ __forceinline__ void mma_f16(float d[4], const uint4& a,
                                        uint32_t b0, uint32_t b1) {
    asm volatile(
        "mma.sync.aligned.m16n8k16.row.col.f32.f16.f16.f32 "
        "{%0,%1,%2,%3}, {%4,%5,%6,%7}, {%8,%9}, {%0,%1,%2,%3};"
        : "+f"(d[0]), "+f"(d[1]), "+f"(d[2]), "+f"(d[3])
        : "r"(a.x), "r"(a.y), "r"(a.z), "r"(a.w),
          "r"(b0), "r"(b1));
}

// ---------------------------------------------------------------------------
// A-in-registers GEMM: 256 threads (8 warps), 255 regs/thread.
// Warp w owns feature rows [m0 + 16w, m0 + 16w + 16); its A fragments for all
// 16 k-steps live in 16 uint4 registers (loaded straight from GMEM, fp32->fp16,
// never touching SMEM). Mainloop k-step: 4 x LDS.128 (paired-B slabs) feeding
// 8 MMAs (U=8 -> full 64-proto chunk per warp). Chunk c-1's 48 stores are
// interleaved into chunk c's 16 k-steps (R13's pipelined-store skeleton).
//   B PAIR slab (pair p, kstep s): 32 lanes x uint4 = 512 B,
//     uint4 = {b0(u=2p), b1(u=2p), b0(u=2p+1), b1(u=2p+1)}
// ---------------------------------------------------------------------------
__global__ void __launch_bounds__(256, 1) proto_dist_kernel(
    const float* __restrict__ feat,
    const float* __restrict__ proto,
    float* __restrict__ out1,    // [N, P]
    float* __restrict__ out2)    // [P, N]
{
    extern __shared__ char smem[];
    float* s_psq = (float*)(smem + SM_PSQ);

    const int tid  = threadIdx.x;
    const int lane = tid & 31;
    const int wid  = tid >> 5;     // 0..7
    const int g    = lane >> 2;
    const int tig  = lane & 3;
    const int m0   = blockIdx.x * BLK_M;

    // ---- A tile into REGISTERS (16 uint4) + exact fp32 feature norms ----
    uint4 aF[16];
    float fs0, fs1;
    {
        const float* rA = feat + (size_t)(m0 + wid * 16 + g) * DIMK;
        const float* rB = rA + 8 * DIMK;
        float sqA = 0.f, sqB = 0.f;
#pragma unroll
        for (int s = 0; s < 16; s++) {
            const int kA = s * 16 + 2 * tig;
            float2 f0 = *(const float2*)(rA + kA);
            float2 f1 = *(const float2*)(rB + kA);
            float2 f2 = *(const float2*)(rA + kA + 8);
            float2 f3 = *(const float2*)(rB + kA + 8);
            sqA += f0.x * f0.x + f0.y * f0.y + f2.x * f2.x + f2.y * f2.y;
            sqB += f1.x * f1.x + f1.y * f1.y + f3.x * f3.x + f3.y * f3.y;
            aF[s].x = pk(f0); aF[s].y = pk(f1); aF[s].z = pk(f2); aF[s].w = pk(f3);
        }
        // quad-reduce over tig: k-slices {16s+2tig, +1, +8, +9} cover full rows
        sqA += __shfl_xor_sync(0xffffffffu, sqA, 1);
        sqA += __shfl_xor_sync(0xffffffffu, sqA, 2);
        sqB += __shfl_xor_sync(0xffffffffu, sqB, 1);
        sqB += __shfl_xor_sync(0xffffffffu, sqB, 2);
        fs0 = sqA;   // norm of row m0 + 16*wid + g
        fs1 = sqB;   // norm of row m0 + 16*wid + g + 8
    }

    // ---- All 512 prototype norms, exact fp32 (proto is L2-hot: 512 KB) ----
#pragma unroll
    for (int rr = 0; rr < 2; rr++) {
        const int row = rr * 256 + tid;
        const float4* r = (const float4*)(proto + (size_t)row * DIMK);
        float s0 = 0.f, s1 = 0.f;
#pragma unroll
        for (int j = 0; j < 64; j += 2) {
            float4 v0 = r[j], v1 = r[j + 1];
            s0 += v0.x * v0.x + v0.y * v0.y + v0.z * v0.z + v0.w * v0.w;
            s1 += v1.x * v1.x + v1.y * v1.y + v1.z * v1.z + v1.w * v1.w;
        }
        s_psq[row] = s0 + s1;
    }

    // ---- B staging: warp w stages ntile u=w of chunk c (paired layout) ----
    auto stage_B = [&](int c, char* buf) {
        const float* r = proto + (size_t)(c * BLK_N + wid * 8 + g) * DIMK;
        char* dst = buf + (wid >> 1) * 8192 + (wid & 1) * 8 + (size_t)lane * 16;
#pragma unroll
        for (int s = 0; s < 16; s++) {
            const int kA = s * 16 + 2 * tig;
            float2 f0 = *(const float2*)(r + kA);
            float2 f1 = *(const float2*)(r + kA + 8);
            uint2 w;
            w.x = pk(f0); w.y = pk(f1);
            *(uint2*)(dst + (size_t)s * 512) = w;
        }
    };

    stage_B(0, smem + SM_B0);
    __syncthreads();   // psq + B(chunk 0) visible

    // Per-warp epilogue constants
    const int ml0 = wid * 16 + g, ml1 = ml0 + 8;
    float* const row1a = out1 + (size_t)(m0 + ml0) * N_PROTO;
    float* const row1b = out1 + (size_t)(m0 + ml1) * N_PROTO;
    const int mcol0 = m0 + ml0, mcol1 = m0 + ml1;
    const int plbase = 2 * tig;

    float accA[8][4], accB[8][4];

    // compute accC from bufC; store pend (chunk at proto offset p0p) if has_pend
    auto run_chunk = [&](float (&accC)[8][4], float (&pend)[8][4],
                         const char* bufC, bool has_pend, int p0p) {
#pragma unroll
        for (int up = 0; up < 8; up++)
#pragma unroll
            for (int e = 0; e < 4; e++) accC[up][e] = 0.f;

        if (has_pend) {
            // transform pending accumulators into distances, in place
#pragma unroll
            for (int up = 0; up < 8; up++) {
                const int pl = plbase + up * 8;
                const float2 ps = *(const float2*)(s_psq + p0p + pl);
                float* d = pend[up];
                d[0] = fs0 + ps.x - 2.0f * d[0];
                d[1] = fs0 + ps.y - 2.0f * d[1];
                d[2] = fs1 + ps.x - 2.0f * d[2];
                d[3] = fs1 + ps.y - 2.0f * d[3];
            }
        }

        const char* bB = bufC + (size_t)lane * 16;

#pragma unroll
        for (int s = 0; s < 16; s++) {
            uint4 bp[4];
#pragma unroll
            for (int p = 0; p < 4; p++)
                bp[p] = *(const uint4*)(bB + p * 8192 + (size_t)s * 512);
#pragma unroll
            for (int p = 0; p < 4; p++) {
                mma_f16(accC[2 * p],     aF[s], bp[p].x, bp[p].y);
                mma_f16(accC[2 * p + 1], aF[s], bp[p].z, bp[p].w);
            }

            // interleave pending stores: up = s>>1; even s -> out1, odd -> out2
            if (has_pend) {
                const int up = s >> 1;
                const int pl = plbase + up * 8;
                const float* d = pend[up];
                if ((s & 1) == 0) {
                    // out1 [N,P]: 4 tig-lanes x float2 = full 32B sector per row
                    *(float2*)(row1a + p0p + pl) = make_float2(d[0], d[1]);
                    *(float2*)(row1b + p0p + pl) = make_float2(d[2], d[3]);
                } else {
                    // out2 [P,N]: 8 g-lanes x 4B = full 32B sector per column
                    out2[(size_t)(p0p + pl)     * N_FEAT + mcol0] = d[0];
                    out2[(size_t)(p0p + pl + 1) * N_FEAT + mcol0] = d[1];
                    out2[(size_t)(p0p + pl)     * N_FEAT + mcol1] = d[2];
                    out2[(size_t)(p0p + pl + 1) * N_FEAT + mcol1] = d[3];
                }
            }
        }
    };

    for (int c2 = 0; c2 < N_CHUNKS / 2; c2++) {
        const int cA = 2 * c2, cB = 2 * c2 + 1;
        // phase A: compute chunk cA (buf0); store chunk cA-1 (accB)
        stage_B(cB, smem + SM_B1);
        run_chunk(accA, accB, smem + SM_B0, c2 > 0, (cA - 1) * BLK_N);
        __syncthreads();   // buf1 ready; buf0 consumed
        // phase B: compute chunk cB (buf1); store chunk cA (accA)
        if (cB + 1 < N_CHUNKS) stage_B(cB + 1, smem + SM_B0);
        run_chunk(accB, accA, smem + SM_B1, true, cA * BLK_N);
        __syncthreads();   // buf0 ready; buf1 consumed
    }

    // ---- tail: store chunk N_CHUNKS-1 from accB ----
    {
        const int p0p = (N_CHUNKS - 1) * BLK_N;
#pragma unroll
        for (int up = 0; up < 8; up++) {
            const int pl = plbase + up * 8;
            const float2 ps = *(const float2*)(s_psq + p0p + pl);
            float* d = accB[up];
            d[0] = fs0 + ps.x - 2.0f * d[0];
            d[1] = fs0 + ps.y - 2.0f * d[1];
            d[2] = fs1 + ps.x - 2.0f * d[2];
            d[3] = fs1 + ps.y - 2.0f * d[3];
            *(float2*)(row1a + p0p + pl) = make_float2(d[0], d[1]);
            *(float2*)(row1b + p0p + pl) = make_float2(d[2], d[3]);
            out2[(size_t)(p0p + pl)     * N_FEAT + mcol0] = d[0];
            out2[(size_t)(p0p + pl + 1) * N_FEAT + mcol0] = d[1];
            out2[(size_t)(p0p + pl)     * N_FEAT + mcol1] = d[2];
            out2[(size_t)(p0p + pl + 1) * N_FEAT + mcol1] = d[3];
        }
    }
}

// ---------------------------------------------------------------------------
// Launch
// ---------------------------------------------------------------------------
extern "C" void kernel_launch(void* const* d_in, const int* in_sizes, int n_in,
                              void* d_out, int out_size)
{
    (void)in_sizes; (void)n_in; (void)out_size;
    const float* feat  = (const float*)d_in[0];
    const float* proto = (const float*)d_in[1];
    float* out1 = (float*)d_out;
    float* out2 = out1 + (size_t)N_FEAT * N_PROTO;

    cudaFuncSetAttribute(proto_dist_kernel,
                         cudaFuncAttributeMaxDynamicSharedMemorySize, SMEM_TOTAL);

    proto_dist_kernel<<<N_FEAT / BLK_M, 256, SMEM_TOTAL>>>(feat, proto, out1, out2);
}

// round 16
// speedup vs baseline: 1.2560x; 1.2560x over previous
#include <cuda_runtime.h>
#include <cuda_fp16.h>
#include <cstdint>

// Problem constants
#define N_FEAT  65536
#define N_PROTO 512
#define DIMK    256

#define BLK_M   256                 // feature rows per CTA (16 warps x 16 rows)
#define BLK_N   16                  // protos per chunk (2 ntiles)
#define N_CHUNKS 32

// SMEM layout (bytes): no A tile, no fsq — A lives in registers.
#define SM_PSQ   0                          // 512 floats = 2048 B
#define SM_B0    4096                       // 16 ksteps * 512 B = 8192
#define SM_B1    (SM_B0 + 8192)
#define SMEM_TOTAL (SM_B1 + 8192)           // 20480 B

// pack float2 -> fp16x2 (x -> low half)
__device__ __forceinline__ uint32_t pk(float2 f) {
    __half2 h = __floats2half2_rn(f.x, f.y);
    return *(uint32_t*)&h;
}

// m16n8k16 fp16 MMA, fp32 accumulate
__device__ __forceinline__ void mma_f16(float d[4], const uint4& a,
                                        uint32_t b0, uint32_t b1) {
    asm volatile(
        "mma.sync.aligned.m16n8k16.row.col.f32.f16.f16.f32 "
        "{%0,%1,%2,%3}, {%4,%5,%6,%7}, {%8,%9}, {%0,%1,%2,%3};"
        : "+f"(d[0]), "+f"(d[1]), "+f"(d[2]), "+f"(d[3])
        : "r"(a.x), "r"(a.y), "r"(a.z), "r"(a.w),
          "r"(b0), "r"(b1));
}

// ---------------------------------------------------------------------------
// A-in-registers GEMM at 512 threads: warp w owns feature rows
// [m0+16w, m0+16w+16); its A fragments for all 16 k-steps are 16 uint4
// registers (GMEM -> fp16 -> regs; A never touches SMEM). Mainloop k-step:
// ONE LDS.128 (paired-B slab) feeding 2 MMAs. Chunk c-1's 12 stores are
// interleaved one per k-step into chunk c (R13's pipelined-store skeleton).
//   B PAIR slab (kstep s): 32 lanes x uint4 = 512 B,
//     uint4 = {b0(u=0), b1(u=0), b0(u=1), b1(u=1)}   (two 8-proto ntiles)
// ---------------------------------------------------------------------------
__global__ void __launch_bounds__(512, 1) proto_dist_kernel(
    const float* __restrict__ feat,
    const float* __restrict__ proto,
    float* __restrict__ out1,    // [N, P]
    float* __restrict__ out2)    // [P, N]
{
    extern __shared__ char smem[];
    float* s_psq = (float*)(smem + SM_PSQ);

    const int tid  = threadIdx.x;
    const int lane = tid & 31;
    const int wid  = tid >> 5;     // 0..15
    const int g    = lane >> 2;
    const int tig  = lane & 3;
    const int m0   = blockIdx.x * BLK_M;

    // ---- A rows into REGISTERS (16 uint4) + exact fp32 feature norms ----
    uint4 aF[16];
    float fs0, fs1;
    {
        const float* rA = feat + (size_t)(m0 + wid * 16 + g) * DIMK;
        const float* rB = rA + 8 * DIMK;
        float sqA = 0.f, sqB = 0.f;
#pragma unroll
        for (int s = 0; s < 16; s++) {
            const int kA = s * 16 + 2 * tig;
            float2 f0 = *(const float2*)(rA + kA);
            float2 f1 = *(const float2*)(rB + kA);
            float2 f2 = *(const float2*)(rA + kA + 8);
            float2 f3 = *(const float2*)(rB + kA + 8);
            sqA += f0.x * f0.x + f0.y * f0.y + f2.x * f2.x + f2.y * f2.y;
            sqB += f1.x * f1.x + f1.y * f1.y + f3.x * f3.x + f3.y * f3.y;
            aF[s].x = pk(f0); aF[s].y = pk(f1); aF[s].z = pk(f2); aF[s].w = pk(f3);
        }
        // quad-reduce over tig: k-slices {16s+2tig,+1,+8,+9} cover full rows
        sqA += __shfl_xor_sync(0xffffffffu, sqA, 1);
        sqA += __shfl_xor_sync(0xffffffffu, sqA, 2);
        sqB += __shfl_xor_sync(0xffffffffu, sqB, 1);
        sqB += __shfl_xor_sync(0xffffffffu, sqB, 2);
        fs0 = sqA;   // norm of row m0 + 16*wid + g
        fs1 = sqB;   // norm of row m0 + 16*wid + g + 8
    }

    // ---- All 512 prototype norms, exact fp32 (one thread per proto) ----
    {
        const float4* r = (const float4*)(proto + (size_t)tid * DIMK);
        float s0 = 0.f, s1 = 0.f, s2 = 0.f, s3 = 0.f;
#pragma unroll
        for (int j = 0; j < 64; j += 4) {
            float4 v0 = r[j], v1 = r[j + 1], v2 = r[j + 2], v3 = r[j + 3];
            s0 += v0.x * v0.x + v0.y * v0.y + v0.z * v0.z + v0.w * v0.w;
            s1 += v1.x * v1.x + v1.y * v1.y + v1.z * v1.z + v1.w * v1.w;
            s2 += v2.x * v2.x + v2.y * v2.y + v2.z * v2.z + v2.w * v2.w;
            s3 += v3.x * v3.x + v3.y * v3.y + v3.z * v3.z + v3.w * v3.w;
        }
        s_psq[tid] = (s0 + s1) + (s2 + s3);
    }

    // ---- B staging: warp w builds kstep s = w of the chunk's pair slab ----
    auto stage_B = [&](int c, char* buf) {
        const int p0 = c * BLK_N;
        const float* r0 = proto + (size_t)(p0 + g) * DIMK;       // ntile u=0
        const float* r1 = proto + (size_t)(p0 + 8 + g) * DIMK;   // ntile u=1
        const int kA = wid * 16 + 2 * tig;
        float2 f0 = *(const float2*)(r0 + kA);
        float2 f2 = *(const float2*)(r0 + kA + 8);
        float2 f1 = *(const float2*)(r1 + kA);
        float2 f3 = *(const float2*)(r1 + kA + 8);
        uint4 w;
        w.x = pk(f0); w.y = pk(f2);   // b0,b1 of u=0
        w.z = pk(f1); w.w = pk(f3);   // b0,b1 of u=1
        *(uint4*)(buf + (size_t)(wid * 32 + lane) * 16) = w;
    };

    stage_B(0, smem + SM_B0);
    __syncthreads();   // psq + B(chunk 0) visible

    // Per-warp epilogue constants
    const int ml0 = wid * 16 + g, ml1 = ml0 + 8;
    float* const row1a = out1 + (size_t)(m0 + ml0) * N_PROTO;
    float* const row1b = out1 + (size_t)(m0 + ml1) * N_PROTO;
    float* const col2a = out2 + (m0 + ml0);   // + p*N_FEAT
    float* const col2b = out2 + (m0 + ml1);
    const int plq = 2 * tig;

    float accA[2][4], accB[2][4];

    // compute accC from bufC; store pend (chunk at proto offset p0p) if has_pend
    auto run_chunk = [&](float (&accC)[2][4], float (&pend)[2][4],
                         const char* bufC, bool has_pend, int p0p) {
#pragma unroll
        for (int up = 0; up < 2; up++)
#pragma unroll
            for (int e = 0; e < 4; e++) accC[up][e] = 0.f;

        if (has_pend) {
            // transform pending accumulators into distances, in place
#pragma unroll
            for (int up = 0; up < 2; up++) {
                const float2 ps = *(const float2*)(s_psq + p0p + plq + up * 8);
                float* d = pend[up];
                d[0] = fs0 + ps.x - 2.0f * d[0];
                d[1] = fs0 + ps.y - 2.0f * d[1];
                d[2] = fs1 + ps.x - 2.0f * d[2];
                d[3] = fs1 + ps.y - 2.0f * d[3];
            }
        }

        const char* bB = bufC + (size_t)lane * 16;

#pragma unroll
        for (int s = 0; s < 16; s++) {
            const uint4 bp = *(const uint4*)(bB + (size_t)s * 512);
            mma_f16(accC[0], aF[s], bp.x, bp.y);
            mma_f16(accC[1], aF[s], bp.z, bp.w);

            // interleave chunk c-1's 12 stores, one per k-step
            if (has_pend && s < 12) {
                if (s < 4) {
                    // out1 [N,P]: 4 tig-lanes x float2 = full 32B sector
                    const int up = s & 1;
                    const float* d = pend[up];
                    if (s < 2) *(float2*)(row1a + p0p + plq + up * 8) = make_float2(d[0], d[1]);
                    else       *(float2*)(row1b + p0p + plq + up * 8) = make_float2(d[2], d[3]);
                } else {
                    // out2 [P,N]: 8 g-lanes x 4B = full 32B sector per column
                    const int q  = s - 4;          // 0..7
                    const int up = q >> 2;         // 0,1
                    const int cc = (q >> 1) & 1;   // column: pl or pl+1
                    const int rr = q & 1;          // row half: a or b
                    const size_t off = (size_t)(p0p + plq + up * 8 + cc) * N_FEAT;
                    const float* d = pend[up];
                    if (rr == 0) col2a[off] = d[cc];
                    else         col2b[off] = d[2 + cc];
                }
            }
        }
    };

    for (int c2 = 0; c2 < N_CHUNKS / 2; c2++) {
        const int cA = 2 * c2, cB = 2 * c2 + 1;
        // phase A: compute chunk cA (buf0); store chunk cA-1 (accB)
        stage_B(cB, smem + SM_B1);
        run_chunk(accA, accB, smem + SM_B0, c2 > 0, (cA - 1) * BLK_N);
        __syncthreads();   // buf1 ready; buf0 consumed
        // phase B: compute chunk cB (buf1); store chunk cA (accA)
        if (cB + 1 < N_CHUNKS) stage_B(cB + 1, smem + SM_B0);
        run_chunk(accB, accA, smem + SM_B1, true, cA * BLK_N);
        __syncthreads();   // buf0 ready; buf1 consumed
    }

    // ---- tail: store chunk N_CHUNKS-1 from accB ----
    {
        const int p0p = (N_CHUNKS - 1) * BLK_N;
#pragma unroll
        for (int up = 0; up < 2; up++) {
            const int pl = plq + up * 8;
            const float2 ps = *(const float2*)(s_psq + p0p + pl);
            float* d = accB[up];
            d[0] = fs0 + ps.x - 2.0f * d[0];
            d[1] = fs0 + ps.y - 2.0f * d[1];
            d[2] = fs1 + ps.x - 2.0f * d[2];
            d[3] = fs1 + ps.y - 2.0f * d[3];
            *(float2*)(row1a + p0p + pl) = make_float2(d[0], d[1]);
            *(float2*)(row1b + p0p + pl) = make_float2(d[2], d[3]);
            col2a[(size_t)(p0p + pl)     * N_FEAT] = d[0];
            col2a[(size_t)(p0p + pl + 1) * N_FEAT] = d[1];
            col2b[(size_t)(p0p + pl)     * N_FEAT] = d[2];
            col2b[(size_t)(p0p + pl + 1) * N_FEAT] = d[3];
        }
    }
}

// ---------------------------------------------------------------------------
// Launch
// ---------------------------------------------------------------------------
extern "C" void kernel_launch(void* const* d_in, const int* in_sizes, int n_in,
                              void* d_out, int out_size)
{
    (void)in_sizes; (void)n_in; (void)out_size;
    const float* feat  = (const float*)d_in[0];
    const float* proto = (const float*)d_in[1];
    float* out1 = (float*)d_out;
    float* out2 = out1 + (size_t)N_FEAT * N_PROTO;

    cudaFuncSetAttribute(proto_dist_kernel,
                         cudaFuncAttributeMaxDynamicSharedMemorySize, SMEM_TOTAL);

    proto_dist_kernel<<<N_FEAT / BLK_M, 512, SMEM_TOTAL>>>(feat, proto, out1, out2);
}